// round 13
// baseline (speedup 1.0000x reference)
#include <cuda_runtime.h>

#define T_LEN 1024
#define B_SZ  32
#define H_SZ  8
#define D_SZ  32
#define YD_SZ 97
#define IN_SZ 256
#define NTHREADS 256  // 8 warps
#define NSM 152       // GB300 SM count (wave size for co-residency pairing)

typedef unsigned long long u64;

// FWM per-step outputs (T,B,H*D) = (T*B, 256) row-major
__device__ float g_scratch[T_LEN * B_SZ * IN_SZ];

// ---- packed f32x2 primitives (Blackwell FFMA2; PTX-only path) ----
__device__ __forceinline__ void ffma2(u64 &d, u64 a, u64 b) {
    asm("fma.rn.f32x2 %0, %1, %2, %0;" : "+l"(d) : "l"(a), "l"(b));
}
__device__ __forceinline__ u64 add2(u64 a, u64 b) {
    u64 r; asm("add.rn.f32x2 %0, %1, %2;" : "=l"(r) : "l"(a), "l"(b));
    return r;
}
__device__ __forceinline__ float2 u2f2(u64 v) {
    float2 r; asm("mov.b64 {%0, %1}, %2;" : "=f"(r.x), "=f"(r.y) : "l"(v));
    return r;
}
__device__ __forceinline__ u64 f2u2(float lo, float hi) {
    u64 r; asm("mov.b64 %0, {%1, %2};" : "=l"(r) : "f"(lo), "f"(hi));
    return r;
}
__device__ __forceinline__ float hsum2(u64 a, u64 b) {
    float2 s = u2f2(add2(a, b));
    return s.x + s.y;
}

// No-max softmax (shift-invariance; pre-activations are O(1) here).
__device__ __forceinline__ float warp_softmax32(float v) {
    float e = __expf(fminf(v, 80.0f));
    float s = e;
#pragma unroll
    for (int o = 16; o > 0; o >>= 1)
        s += __shfl_xor_sync(0xffffffffu, s, o);
    return __fdividef(e, s);
}

// Roles: 0=q 1=k 2=fq 3=fk 4=x-pipe 5=FWM 6=beta/fb 7=fv
// Per-CTA SMSP loads (role pairs on wid%4): S0{q,xp}=130 S1{k,FWM}=180
// S2{fq,beta}=125 S3{fk,fv}=190.  Co-resident CTAs are (bid, bid+NSM);
// wave-2 CTAs use role = wid^1, so per-SM SMSP sums flatten to
// {310,310,315,315} instead of {260,360,250,380}.
__global__ __launch_bounds__(NTHREADS)
void srwm_scan_kernel(const float* __restrict__ h_in,
                      const float* __restrict__ W_y,
                      const float* __restrict__ W_q,
                      const float* __restrict__ W_k,
                      const float* __restrict__ w_b,
                      const float* __restrict__ sWy,
                      const float* __restrict__ sWq,
                      const float* __restrict__ sWk,
                      const float* __restrict__ swb,
                      const float* __restrict__ Fw)
{
    const int bh   = blockIdx.x;      // 256 chains
    const int b    = bh >> 3;         // 0..31
    const int hh   = bh & 7;          // 0..7
    const int tid  = threadIdx.x;
    const int wid  = tid >> 5;
    const int lane = tid & 31;
    const int role = (blockIdx.x >= NSM) ? (wid ^ 1) : wid;

    __shared__ __align__(16) float xbuf[2][D_SZ];
    __shared__ __align__(16) float qsh[2][D_SZ], ksh[2][D_SZ];
    __shared__ __align__(16) float fqsh[2][D_SZ], fksh[2][D_SZ], fvsh[2][D_SZ];
    __shared__ float betash[2][4];
    __shared__ float fbsh[2];

    // Column state: 16 packed (d, d+1) fp32 pairs, resident in registers.
    u64 col[D_SZ / 2];
#pragma unroll
    for (int i = 0; i < D_SZ / 2; i++) col[i] = 0ull;

    // ---- init state columns (per role) ----
    if (role == 0) {                      // q: Wq column `lane`
        const float* g = W_q + hh * D_SZ * D_SZ;
        const float* s = sWq + (size_t)(b * H_SZ + hh) * D_SZ * D_SZ;
#pragma unroll
        for (int i = 0; i < 16; i++)
            col[i] = f2u2(g[(2*i)*D_SZ + lane]   + s[(2*i)*D_SZ + lane],
                          g[(2*i+1)*D_SZ + lane] + s[(2*i+1)*D_SZ + lane]);
    } else if (role == 1) {               // k: Wk column `lane`
        const float* g = W_k + hh * D_SZ * D_SZ;
        const float* s = sWk + (size_t)(b * H_SZ + hh) * D_SZ * D_SZ;
#pragma unroll
        for (int i = 0; i < 16; i++)
            col[i] = f2u2(g[(2*i)*D_SZ + lane]   + s[(2*i)*D_SZ + lane],
                          g[(2*i+1)*D_SZ + lane] + s[(2*i+1)*D_SZ + lane]);
    } else if (role == 2 || role == 3 || role == 7) {  // fq / fk / fv: Wy cols
        const int j = (role == 2 ? 0 : role == 3 ? 32 : 64) + lane;
        const float* g = W_y + hh * D_SZ * YD_SZ;
        const float* s = sWy + (size_t)(b * H_SZ + hh) * D_SZ * YD_SZ;
#pragma unroll
        for (int i = 0; i < 16; i++)
            col[i] = f2u2(g[(2*i)*YD_SZ + j]   + s[(2*i)*YD_SZ + j],
                          g[(2*i+1)*YD_SZ + j] + s[(2*i+1)*YD_SZ + j]);
    } else if (role == 6 && lane < 5) {   // beta/fb columns
        if (lane == 0) {                  // fb: Wy col 96
            const float* g = W_y + hh * D_SZ * YD_SZ;
            const float* s = sWy + (size_t)(b * H_SZ + hh) * D_SZ * YD_SZ;
#pragma unroll
            for (int i = 0; i < 16; i++)
                col[i] = f2u2(g[(2*i)*YD_SZ + 96]   + s[(2*i)*YD_SZ + 96],
                              g[(2*i+1)*YD_SZ + 96] + s[(2*i+1)*YD_SZ + 96]);
        } else {                          // wb col lane-1
            const int j = lane - 1;
            const float* g = w_b + hh * D_SZ * 4;
            const float* s = swb + (size_t)(b * H_SZ + hh) * D_SZ * 4;
#pragma unroll
            for (int i = 0; i < 16; i++)
                col[i] = f2u2(g[(2*i)*4 + j]   + s[(2*i)*4 + j],
                              g[(2*i+1)*4 + j] + s[(2*i+1)*4 + j]);
        }
    } else if (role == 5) {               // FWM: F column `lane`
        const float* f = Fw + (size_t)(b * H_SZ + hh) * D_SZ * D_SZ;
#pragma unroll
        for (int i = 0; i < 16; i++)
            col[i] = f2u2(f[(2*i)*D_SZ + lane], f[(2*i+1)*D_SZ + lane]);
    }

    // x-pipe role owns the x softmax pipeline.
    float xreg = 0.f;
    const float* hbase = h_in + (size_t)b * IN_SZ + hh * D_SZ + lane;
    if (role == 4) {
        xbuf[0][lane] = warp_softmax32(hbase[0]);
        xreg = hbase[(size_t)1 * B_SZ * IN_SZ];
    }
    float* scr_base = g_scratch + (size_t)b * IN_SZ + hh * D_SZ + lane;
    const u64 NEG1 = f2u2(-1.0f, -1.0f);
    __syncthreads();

    for (int t = 0; t < T_LEN; ++t) {
        const int p = t & 1;
        const ulonglong2* x2 = reinterpret_cast<const ulonglong2*>(xbuf[p]);

        // ---- phase 1 ----
        if (role <= 3 || role == 7) {
            u64 a0 = 0ull, a1 = 0ull, a2 = 0ull, a3 = 0ull;
#pragma unroll
            for (int i = 0; i < 8; i += 2) {
                ulonglong2 xv0 = x2[i];
                ulonglong2 xv1 = x2[i + 1];
                ffma2(a0, xv0.x, col[2*i + 0]);
                ffma2(a1, xv0.y, col[2*i + 1]);
                ffma2(a2, xv1.x, col[2*i + 2]);
                ffma2(a3, xv1.y, col[2*i + 3]);
            }
            float raw = hsum2(add2(a0, a1), add2(a2, a3));
            if      (role == 0) qsh[p][lane]  = warp_softmax32(raw);
            else if (role == 1) ksh[p][lane]  = warp_softmax32(raw);
            else if (role == 2) fqsh[p][lane] = warp_softmax32(raw);
            else if (role == 3) fksh[p][lane] = warp_softmax32(raw);
            else                fvsh[p][lane] = raw;                  // fv
        } else if (role == 4) {
            // x_{t+1} softmax + prefetch h[t+2]
            xbuf[p ^ 1][lane] = warp_softmax32(xreg);
            if (t + 2 < T_LEN)
                xreg = hbase[(size_t)(t + 2) * B_SZ * IN_SZ];
        } else if (role == 6) {
            if (lane < 5) {
                u64 a0 = 0ull, a1 = 0ull;
#pragma unroll
                for (int i = 0; i < 8; i++) {
                    ulonglong2 xv = x2[i];
                    ffma2(a0, xv.x, col[2*i + 0]);
                    ffma2(a1, xv.y, col[2*i + 1]);
                }
                float raw = hsum2(a0, a1);
                float sg = 1.0f / (1.0f + __expf(-raw));
                if (lane == 0) fbsh[p] = sg;
                else           betash[p][lane - 1] = sg;
            }
        } else if (t > 0) {   // role == 5 : lagged FWM for step t-1
            const int pp = p ^ 1;
            const ulonglong2* fk2 = reinterpret_cast<const ulonglong2*>(fksh[pp]);
            const ulonglong2* fq2 = reinterpret_cast<const ulonglong2*>(fqsh[pp]);
            const float fbv = fbsh[pp];
            const float fvv = fvsh[pp][lane];
            ulonglong2 kreg[8], qreg[8];
            u64 vA = 0ull, vB = 0ull;
#pragma unroll
            for (int i = 0; i < 8; i++) {
                kreg[i] = fk2[i];
                qreg[i] = fq2[i];
                ffma2(vA, kreg[i].x, col[2*i + 0]);
                ffma2(vB, kreg[i].y, col[2*i + 1]);
            }
            const float coeff = fbv * (fvv - hsum2(vA, vB));
            const u64 c2 = f2u2(coeff, coeff);
            u64 oA = 0ull, oB = 0ull;
#pragma unroll
            for (int i = 0; i < 8; i++) {
                ffma2(col[2*i + 0], kreg[i].x, c2);
                ffma2(col[2*i + 1], kreg[i].y, c2);
                ffma2(oA, qreg[i].x, col[2*i + 0]);
                ffma2(oB, qreg[i].y, col[2*i + 1]);
            }
            scr_base[(size_t)(t - 1) * B_SZ * IN_SZ] = hsum2(oA, oB);
        }
        __syncthreads();   // the ONLY barrier per step

        // ---- phase 2: rank-1 SRWM updates, fused (q-k) matvec ----
        if (role <= 3 || role == 7 || (role == 6 && lane < 5)) {
            float bsel;
            if      (role == 0) bsel = betash[p][1];
            else if (role == 1) bsel = betash[p][2];
            else if (role == 6) bsel = (lane == 0) ? betash[p][0] : betash[p][3];
            else                bsel = betash[p][0];   // roles 2,3,7 (Wy)
            const ulonglong2* q2 = reinterpret_cast<const ulonglong2*>(qsh[p]);
            const ulonglong2* k2 = reinterpret_cast<const ulonglong2*>(ksh[p]);
            ulonglong2 kreg[8];
            u64 dvA = 0ull, dvB = 0ull;
#pragma unroll
            for (int i = 0; i < 8; i++) {
                ulonglong2 qv = q2[i];
                kreg[i] = k2[i];
                u64 qmkx = qv.x, qmky = qv.y;
                ffma2(qmkx, kreg[i].x, NEG1);
                ffma2(qmky, kreg[i].y, NEG1);
                ffma2(dvA, qmkx, col[2*i + 0]);
                ffma2(dvB, qmky, col[2*i + 1]);
            }
            const float diff = bsel * hsum2(dvA, dvB);
            const u64 d2 = f2u2(diff, diff);
#pragma unroll
            for (int i = 0; i < 8; i++) {
                ffma2(col[2*i + 0], kreg[i].x, d2);
                ffma2(col[2*i + 1], kreg[i].y, d2);
            }
        }
        // phase1(t+1) writes parity p^1; phase2(t) reads parity p.
        // All cross-parity hazards are separated by the barrier above.
    }

    // Epilogue: FWM for the final step t = T-1.
    if (role == 5) {
        const int pp = (T_LEN - 1) & 1;
        const ulonglong2* fk2 = reinterpret_cast<const ulonglong2*>(fksh[pp]);
        const ulonglong2* fq2 = reinterpret_cast<const ulonglong2*>(fqsh[pp]);
        const float fbv = fbsh[pp];
        const float fvv = fvsh[pp][lane];
        ulonglong2 kreg[8], qreg[8];
        u64 vA = 0ull, vB = 0ull;
#pragma unroll
        for (int i = 0; i < 8; i++) {
            kreg[i] = fk2[i];
            qreg[i] = fq2[i];
            ffma2(vA, kreg[i].x, col[2*i + 0]);
            ffma2(vB, kreg[i].y, col[2*i + 1]);
        }
        const float coeff = fbv * (fvv - hsum2(vA, vB));
        const u64 c2 = f2u2(coeff, coeff);
        u64 oA = 0ull, oB = 0ull;
#pragma unroll
        for (int i = 0; i < 8; i++) {
            ffma2(col[2*i + 0], kreg[i].x, c2);
            ffma2(col[2*i + 1], kreg[i].y, c2);
            ffma2(oA, qreg[i].x, col[2*i + 0]);
            ffma2(oB, qreg[i].y, col[2*i + 1]);
        }
        scr_base[(size_t)(T_LEN - 1) * B_SZ * IN_SZ] = hsum2(oA, oB);
    }
}

// ======================= output projection ==========================
// out[r, i] = h[r, i] + sum_j scratch[r, j] * W_out[i, j]
// (T*B=32768) x 256 x 256 sgemm, 128x128 tiles, 8x8 micro-tiles.
// A-fragments read as packed row-pairs (LDS.128 -> native FFMA2 operands);
// accumulators packed across rows; B splatted. GBK=16 halves barrier count.
#define GBM 128
#define GBN 128
#define GBK 16

__global__ __launch_bounds__(256)
void proj_kernel(const float* __restrict__ W,
                 const float* __restrict__ Hin,
                 float* __restrict__ out)
{
    __shared__ __align__(16) float As[GBK][GBM];
    __shared__ __align__(16) float Bs[GBK][GBN];
    const int row0 = blockIdx.x * GBM;
    const int col0 = blockIdx.y * GBN;
    const int tid  = threadIdx.x;
    const int tr   = (tid / 16) * 8;
    const int tc   = (tid % 16) * 8;

    // acc2[u2][v] = packed (row tr+2*u2, row tr+2*u2+1) for column tc+v
    u64 acc2[4][8];
#pragma unroll
    for (int u = 0; u < 4; u++)
#pragma unroll
        for (int v = 0; v < 8; v++) acc2[u][v] = 0ull;

    const int ar = tid >> 1;          // row / column within tile (0..127)
    const int ak = (tid & 1) * 8;     // k half (0 or 8)

    for (int k0 = 0; k0 < IN_SZ; k0 += GBK) {
        const float* as = &g_scratch[(row0 + ar) * IN_SZ + k0 + ak];
        const float* ws = &W[(col0 + ar) * IN_SZ + k0 + ak];
        float4 av0 = *reinterpret_cast<const float4*>(as);
        float4 av1 = *reinterpret_cast<const float4*>(as + 4);
        float4 bv0 = *reinterpret_cast<const float4*>(ws);
        float4 bv1 = *reinterpret_cast<const float4*>(ws + 4);
        As[ak + 0][ar] = av0.x; As[ak + 1][ar] = av0.y;
        As[ak + 2][ar] = av0.z; As[ak + 3][ar] = av0.w;
        As[ak + 4][ar] = av1.x; As[ak + 5][ar] = av1.y;
        As[ak + 6][ar] = av1.z; As[ak + 7][ar] = av1.w;
        Bs[ak + 0][ar] = bv0.x; Bs[ak + 1][ar] = bv0.y;
        Bs[ak + 2][ar] = bv0.z; Bs[ak + 3][ar] = bv0.w;
        Bs[ak + 4][ar] = bv1.x; Bs[ak + 5][ar] = bv1.y;
        Bs[ak + 6][ar] = bv1.z; Bs[ak + 7][ar] = bv1.w;
        __syncthreads();
#pragma unroll
        for (int k = 0; k < GBK; k++) {
            // packed row pairs (contiguous floats in As row k)
            ulonglong2 a01 = *reinterpret_cast<const ulonglong2*>(&As[k][tr]);
            ulonglong2 a23 = *reinterpret_cast<const ulonglong2*>(&As[k][tr + 4]);
            u64 ap[4] = {a01.x, a01.y, a23.x, a23.y};
            float4 b0 = *reinterpret_cast<const float4*>(&Bs[k][tc]);
            float4 b1 = *reinterpret_cast<const float4*>(&Bs[k][tc + 4]);
            u64 bs[8];
            bs[0] = f2u2(b0.x, b0.x); bs[1] = f2u2(b0.y, b0.y);
            bs[2] = f2u2(b0.z, b0.z); bs[3] = f2u2(b0.w, b0.w);
            bs[4] = f2u2(b1.x, b1.x); bs[5] = f2u2(b1.y, b1.y);
            bs[6] = f2u2(b1.z, b1.z); bs[7] = f2u2(b1.w, b1.w);
#pragma unroll
            for (int u = 0; u < 4; u++)
#pragma unroll
                for (int v = 0; v < 8; v++)
                    ffma2(acc2[u][v], ap[u], bs[v]);
        }
        __syncthreads();
    }

#pragma unroll
    for (int u = 0; u < 4; u++) {
        const int r0 = row0 + tr + 2 * u;
        float lo[8], hi[8];
#pragma unroll
        for (int v = 0; v < 8; v++) {
            float2 t = u2f2(acc2[u][v]);
            lo[v] = t.x; hi[v] = t.y;
        }
#pragma unroll
        for (int half = 0; half < 2; half++) {
            const int c = col0 + tc + half * 4;
            const float* src = half ? (float*)0 : (float*)0; (void)src;
            float4 h0 = *reinterpret_cast<const float4*>(&Hin[r0 * IN_SZ + c]);
            float4 h1 = *reinterpret_cast<const float4*>(&Hin[(r0 + 1) * IN_SZ + c]);
            float4 o0, o1;
            o0.x = h0.x + lo[half*4+0]; o0.y = h0.y + lo[half*4+1];
            o0.z = h0.z + lo[half*4+2]; o0.w = h0.w + lo[half*4+3];
            o1.x = h1.x + hi[half*4+0]; o1.y = h1.y + hi[half*4+1];
            o1.z = h1.z + hi[half*4+2]; o1.w = h1.w + hi[half*4+3];
            *reinterpret_cast<float4*>(&out[r0 * IN_SZ + c]) = o0;
            *reinterpret_cast<float4*>(&out[(r0 + 1) * IN_SZ + c]) = o1;
        }
    }
}

extern "C" void kernel_launch(void* const* d_in, const int* in_sizes, int n_in,
                              void* d_out, int out_size) {
    const float* h_in  = (const float*)d_in[0];
    const float* W_y   = (const float*)d_in[1];
    const float* W_q   = (const float*)d_in[2];
    const float* W_k   = (const float*)d_in[3];
    const float* w_b   = (const float*)d_in[4];
    const float* W_out = (const float*)d_in[5];
    const float* sWy   = (const float*)d_in[6];
    const float* sWq   = (const float*)d_in[7];
    const float* sWk   = (const float*)d_in[8];
    const float* swb   = (const float*)d_in[9];
    const float* Fw    = (const float*)d_in[10];

    srwm_scan_kernel<<<B_SZ * H_SZ, NTHREADS>>>(
        h_in, W_y, W_q, W_k, w_b, sWy, sWq, sWk, swb, Fw);

    dim3 grid((T_LEN * B_SZ) / GBM, IN_SZ / GBN);
    proj_kernel<<<grid, 256>>>(W_out, h_in, (float*)d_out);
}

// round 14
// speedup vs baseline: 1.0467x; 1.0467x over previous
#include <cuda_runtime.h>

#define T_LEN 1024
#define B_SZ  32
#define H_SZ  8
#define D_SZ  32
#define YD_SZ 97
#define IN_SZ 256
#define NTHREADS 256  // 8 warps

typedef unsigned long long u64;

// FWM per-step outputs (T,B,H*D) = (T*B, 256) row-major
__device__ float g_scratch[T_LEN * B_SZ * IN_SZ];

// Per-SM CTA-slot counters (zero-init; restored to zero by decrement at exit).
__device__ int g_smslot[1024];

// Role maps by slot. Roles: 0=q 1=k 2=fq 3=fk 4=xp 5=FWM 6=beta/fb 7=fv
// Issue-load estimates: q/k/fq/fk~120, fv~105, beta~98, FWM~75, xp~35.
// Partition A (slot 0): S0{q,k} S1{fq,b} S2{fv,FWM} S3{fk,xp} = 240/218/180/155
// Partition B (slot 1): S0{fk,xp} S1{fv,FWM} S2{fq,b} S3{q,k} = 155/180/218/240
// Co-resident A+B per-SM SMSP sums: {395,398,398,395}  (vs 450 same-map).
__constant__ int c_mapA[8] = {0, 2, 7, 3, 1, 6, 5, 4};
__constant__ int c_mapB[8] = {3, 7, 2, 0, 4, 5, 6, 1};

// ---- packed f32x2 primitives (Blackwell FFMA2; PTX-only path) ----
__device__ __forceinline__ void ffma2(u64 &d, u64 a, u64 b) {
    asm("fma.rn.f32x2 %0, %1, %2, %0;" : "+l"(d) : "l"(a), "l"(b));
}
__device__ __forceinline__ u64 add2(u64 a, u64 b) {
    u64 r; asm("add.rn.f32x2 %0, %1, %2;" : "=l"(r) : "l"(a), "l"(b));
    return r;
}
__device__ __forceinline__ float2 u2f2(u64 v) {
    float2 r; asm("mov.b64 {%0, %1}, %2;" : "=f"(r.x), "=f"(r.y) : "l"(v));
    return r;
}
__device__ __forceinline__ u64 f2u2(float lo, float hi) {
    u64 r; asm("mov.b64 %0, {%1, %2};" : "=l"(r) : "f"(lo), "f"(hi));
    return r;
}
__device__ __forceinline__ float hsum2(u64 a, u64 b) {
    float2 s = u2f2(add2(a, b));
    return s.x + s.y;
}

// No-max softmax (shift-invariance; pre-activations are O(1) here).
__device__ __forceinline__ float warp_softmax32(float v) {
    float e = __expf(fminf(v, 80.0f));
    float s = e;
#pragma unroll
    for (int o = 16; o > 0; o >>= 1)
        s += __shfl_xor_sync(0xffffffffu, s, o);
    return __fdividef(e, s);
}

__global__ __launch_bounds__(NTHREADS)
void srwm_scan_kernel(const float* __restrict__ h_in,
                      const float* __restrict__ W_y,
                      const float* __restrict__ W_q,
                      const float* __restrict__ W_k,
                      const float* __restrict__ w_b,
                      const float* __restrict__ sWy,
                      const float* __restrict__ sWq,
                      const float* __restrict__ sWk,
                      const float* __restrict__ swb,
                      const float* __restrict__ Fw)
{
    const int bh   = blockIdx.x;      // 256 chains
    const int b    = bh >> 3;         // 0..31
    const int hh   = bh & 7;          // 0..7
    const int tid  = threadIdx.x;
    const int wid  = tid >> 5;
    const int lane = tid & 31;

    __shared__ __align__(16) float xbuf[2][D_SZ];
    __shared__ __align__(16) float qsh[2][D_SZ], ksh[2][D_SZ];
    __shared__ __align__(16) float fqsh[2][D_SZ], fksh[2][D_SZ], fvsh[2][D_SZ];
    __shared__ float betash[2][4];
    __shared__ float fbsh[2];
    __shared__ int slot_sh;

    // SM-local CTA slot: the two co-resident CTAs on an SM get {0,1}
    // regardless of placement. Counter restored to zero at kernel end.
    unsigned int smid;
    asm("mov.u32 %0, %%smid;" : "=r"(smid));
    if (tid == 0) slot_sh = atomicAdd(&g_smslot[smid & 1023], 1);
    __syncthreads();
    const int role = (slot_sh & 1) ? c_mapB[wid] : c_mapA[wid];

    // Column state: 16 packed (d, d+1) fp32 pairs, resident in registers.
    u64 col[D_SZ / 2];
#pragma unroll
    for (int i = 0; i < D_SZ / 2; i++) col[i] = 0ull;

    // ---- init state columns (per role) ----
    if (role == 0) {                      // q: Wq column `lane`
        const float* g = W_q + hh * D_SZ * D_SZ;
        const float* s = sWq + (size_t)(b * H_SZ + hh) * D_SZ * D_SZ;
#pragma unroll
        for (int i = 0; i < 16; i++)
            col[i] = f2u2(g[(2*i)*D_SZ + lane]   + s[(2*i)*D_SZ + lane],
                          g[(2*i+1)*D_SZ + lane] + s[(2*i+1)*D_SZ + lane]);
    } else if (role == 1) {               // k: Wk column `lane`
        const float* g = W_k + hh * D_SZ * D_SZ;
        const float* s = sWk + (size_t)(b * H_SZ + hh) * D_SZ * D_SZ;
#pragma unroll
        for (int i = 0; i < 16; i++)
            col[i] = f2u2(g[(2*i)*D_SZ + lane]   + s[(2*i)*D_SZ + lane],
                          g[(2*i+1)*D_SZ + lane] + s[(2*i+1)*D_SZ + lane]);
    } else if (role == 2 || role == 3 || role == 7) {  // fq / fk / fv: Wy cols
        const int j = (role == 2 ? 0 : role == 3 ? 32 : 64) + lane;
        const float* g = W_y + hh * D_SZ * YD_SZ;
        const float* s = sWy + (size_t)(b * H_SZ + hh) * D_SZ * YD_SZ;
#pragma unroll
        for (int i = 0; i < 16; i++)
            col[i] = f2u2(g[(2*i)*YD_SZ + j]   + s[(2*i)*YD_SZ + j],
                          g[(2*i+1)*YD_SZ + j] + s[(2*i+1)*YD_SZ + j]);
    } else if (role == 6 && lane < 5) {   // beta/fb columns
        if (lane == 0) {                  // fb: Wy col 96
            const float* g = W_y + hh * D_SZ * YD_SZ;
            const float* s = sWy + (size_t)(b * H_SZ + hh) * D_SZ * YD_SZ;
#pragma unroll
            for (int i = 0; i < 16; i++)
                col[i] = f2u2(g[(2*i)*YD_SZ + 96]   + s[(2*i)*YD_SZ + 96],
                              g[(2*i+1)*YD_SZ + 96] + s[(2*i+1)*YD_SZ + 96]);
        } else {                          // wb col lane-1
            const int j = lane - 1;
            const float* g = w_b + hh * D_SZ * 4;
            const float* s = swb + (size_t)(b * H_SZ + hh) * D_SZ * 4;
#pragma unroll
            for (int i = 0; i < 16; i++)
                col[i] = f2u2(g[(2*i)*4 + j]   + s[(2*i)*4 + j],
                              g[(2*i+1)*4 + j] + s[(2*i+1)*4 + j]);
        }
    } else if (role == 5) {               // FWM: F column `lane`
        const float* f = Fw + (size_t)(b * H_SZ + hh) * D_SZ * D_SZ;
#pragma unroll
        for (int i = 0; i < 16; i++)
            col[i] = f2u2(f[(2*i)*D_SZ + lane], f[(2*i+1)*D_SZ + lane]);
    }

    // x-pipe role owns the x softmax pipeline.
    float xreg = 0.f;
    const float* hbase = h_in + (size_t)b * IN_SZ + hh * D_SZ + lane;
    if (role == 4) {
        xbuf[0][lane] = warp_softmax32(hbase[0]);
        xreg = hbase[(size_t)1 * B_SZ * IN_SZ];
    }
    float* scr_base = g_scratch + (size_t)b * IN_SZ + hh * D_SZ + lane;
    const u64 NEG1 = f2u2(-1.0f, -1.0f);
    __syncthreads();

    for (int t = 0; t < T_LEN; ++t) {
        const int p = t & 1;
        const ulonglong2* x2 = reinterpret_cast<const ulonglong2*>(xbuf[p]);

        // ---- phase 1 ----
        if (role <= 3 || role == 7) {
            u64 a0 = 0ull, a1 = 0ull, a2 = 0ull, a3 = 0ull;
#pragma unroll
            for (int i = 0; i < 8; i += 2) {
                ulonglong2 xv0 = x2[i];
                ulonglong2 xv1 = x2[i + 1];
                ffma2(a0, xv0.x, col[2*i + 0]);
                ffma2(a1, xv0.y, col[2*i + 1]);
                ffma2(a2, xv1.x, col[2*i + 2]);
                ffma2(a3, xv1.y, col[2*i + 3]);
            }
            float raw = hsum2(add2(a0, a1), add2(a2, a3));
            if      (role == 0) qsh[p][lane]  = warp_softmax32(raw);
            else if (role == 1) ksh[p][lane]  = warp_softmax32(raw);
            else if (role == 2) fqsh[p][lane] = warp_softmax32(raw);
            else if (role == 3) fksh[p][lane] = warp_softmax32(raw);
            else                fvsh[p][lane] = raw;                  // fv
        } else if (role == 4) {
            // x_{t+1} softmax + prefetch h[t+2]
            xbuf[p ^ 1][lane] = warp_softmax32(xreg);
            if (t + 2 < T_LEN)
                xreg = hbase[(size_t)(t + 2) * B_SZ * IN_SZ];
        } else if (role == 6) {
            if (lane < 5) {
                u64 a0 = 0ull, a1 = 0ull;
#pragma unroll
                for (int i = 0; i < 8; i++) {
                    ulonglong2 xv = x2[i];
                    ffma2(a0, xv.x, col[2*i + 0]);
                    ffma2(a1, xv.y, col[2*i + 1]);
                }
                float raw = hsum2(a0, a1);
                float sg = 1.0f / (1.0f + __expf(-raw));
                if (lane == 0) fbsh[p] = sg;
                else           betash[p][lane - 1] = sg;
            }
        } else if (t > 0) {   // role == 5 : lagged FWM for step t-1
            const int pp = p ^ 1;
            const ulonglong2* fk2 = reinterpret_cast<const ulonglong2*>(fksh[pp]);
            const ulonglong2* fq2 = reinterpret_cast<const ulonglong2*>(fqsh[pp]);
            const float fbv = fbsh[pp];
            const float fvv = fvsh[pp][lane];
            ulonglong2 kreg[8], qreg[8];
            u64 vA = 0ull, vB = 0ull;
#pragma unroll
            for (int i = 0; i < 8; i++) {
                kreg[i] = fk2[i];
                qreg[i] = fq2[i];
                ffma2(vA, kreg[i].x, col[2*i + 0]);
                ffma2(vB, kreg[i].y, col[2*i + 1]);
            }
            const float coeff = fbv * (fvv - hsum2(vA, vB));
            const u64 c2 = f2u2(coeff, coeff);
            u64 oA = 0ull, oB = 0ull;
#pragma unroll
            for (int i = 0; i < 8; i++) {
                ffma2(col[2*i + 0], kreg[i].x, c2);
                ffma2(col[2*i + 1], kreg[i].y, c2);
                ffma2(oA, qreg[i].x, col[2*i + 0]);
                ffma2(oB, qreg[i].y, col[2*i + 1]);
            }
            scr_base[(size_t)(t - 1) * B_SZ * IN_SZ] = hsum2(oA, oB);
        }
        __syncthreads();   // the ONLY barrier per step

        // ---- phase 2: rank-1 SRWM updates, fused (q-k) matvec ----
        if (role <= 3 || role == 7 || (role == 6 && lane < 5)) {
            float bsel;
            if      (role == 0) bsel = betash[p][1];
            else if (role == 1) bsel = betash[p][2];
            else if (role == 6) bsel = (lane == 0) ? betash[p][0] : betash[p][3];
            else                bsel = betash[p][0];   // roles 2,3,7 (Wy)
            const ulonglong2* q2 = reinterpret_cast<const ulonglong2*>(qsh[p]);
            const ulonglong2* k2 = reinterpret_cast<const ulonglong2*>(ksh[p]);
            ulonglong2 kreg[8];
            u64 dvA = 0ull, dvB = 0ull;
#pragma unroll
            for (int i = 0; i < 8; i++) {
                ulonglong2 qv = q2[i];
                kreg[i] = k2[i];
                u64 qmkx = qv.x, qmky = qv.y;
                ffma2(qmkx, kreg[i].x, NEG1);
                ffma2(qmky, kreg[i].y, NEG1);
                ffma2(dvA, qmkx, col[2*i + 0]);
                ffma2(dvB, qmky, col[2*i + 1]);
            }
            const float diff = bsel * hsum2(dvA, dvB);
            const u64 d2 = f2u2(diff, diff);
#pragma unroll
            for (int i = 0; i < 8; i++) {
                ffma2(col[2*i + 0], kreg[i].x, d2);
                ffma2(col[2*i + 1], kreg[i].y, d2);
            }
        }
        // phase1(t+1) writes parity p^1; phase2(t) reads parity p.
        // All cross-parity hazards are separated by the barrier above.
    }

    // Epilogue: FWM for the final step t = T-1.
    if (role == 5) {
        const int pp = (T_LEN - 1) & 1;
        const ulonglong2* fk2 = reinterpret_cast<const ulonglong2*>(fksh[pp]);
        const ulonglong2* fq2 = reinterpret_cast<const ulonglong2*>(fqsh[pp]);
        const float fbv = fbsh[pp];
        const float fvv = fvsh[pp][lane];
        ulonglong2 kreg[8], qreg[8];
        u64 vA = 0ull, vB = 0ull;
#pragma unroll
        for (int i = 0; i < 8; i++) {
            kreg[i] = fk2[i];
            qreg[i] = fq2[i];
            ffma2(vA, kreg[i].x, col[2*i + 0]);
            ffma2(vB, kreg[i].y, col[2*i + 1]);
        }
        const float coeff = fbv * (fvv - hsum2(vA, vB));
        const u64 c2 = f2u2(coeff, coeff);
        u64 oA = 0ull, oB = 0ull;
#pragma unroll
        for (int i = 0; i < 8; i++) {
            ffma2(col[2*i + 0], kreg[i].x, c2);
            ffma2(col[2*i + 1], kreg[i].y, c2);
            ffma2(oA, qreg[i].x, col[2*i + 0]);
            ffma2(oB, qreg[i].y, col[2*i + 1]);
        }
        scr_base[(size_t)(T_LEN - 1) * B_SZ * IN_SZ] = hsum2(oA, oB);
    }

    // Restore the per-SM slot counter to zero for the next launch/replay.
    if (tid == 0) atomicSub(&g_smslot[smid & 1023], 1);
}

// ======================= output projection ==========================
// out[r, i] = h[r, i] + sum_j scratch[r, j] * W_out[i, j]
// (T*B=32768) x 256 x 256 sgemm, 128x128 tiles, 8x8 micro-tiles.
// A-fragments read as packed row-pairs (LDS.128 -> native FFMA2 operands);
// accumulators packed across rows; B splatted. GBK=16 halves barrier count.
#define GBM 128
#define GBN 128
#define GBK 16

__global__ __launch_bounds__(256)
void proj_kernel(const float* __restrict__ W,
                 const float* __restrict__ Hin,
                 float* __restrict__ out)
{
    __shared__ __align__(16) float As[GBK][GBM];
    __shared__ __align__(16) float Bs[GBK][GBN];
    const int row0 = blockIdx.x * GBM;
    const int col0 = blockIdx.y * GBN;
    const int tid  = threadIdx.x;
    const int tr   = (tid / 16) * 8;
    const int tc   = (tid % 16) * 8;

    // acc2[u2][v] = packed (row tr+2*u2, row tr+2*u2+1) for column tc+v
    u64 acc2[4][8];
#pragma unroll
    for (int u = 0; u < 4; u++)
#pragma unroll
        for (int v = 0; v < 8; v++) acc2[u][v] = 0ull;

    const int ar = tid >> 1;          // row / column within tile (0..127)
    const int ak = (tid & 1) * 8;     // k half (0 or 8)

    for (int k0 = 0; k0 < IN_SZ; k0 += GBK) {
        const float* as = &g_scratch[(row0 + ar) * IN_SZ + k0 + ak];
        const float* ws = &W[(col0 + ar) * IN_SZ + k0 + ak];
        float4 av0 = *reinterpret_cast<const float4*>(as);
        float4 av1 = *reinterpret_cast<const float4*>(as + 4);
        float4 bv0 = *reinterpret_cast<const float4*>(ws);
        float4 bv1 = *reinterpret_cast<const float4*>(ws + 4);
        As[ak + 0][ar] = av0.x; As[ak + 1][ar] = av0.y;
        As[ak + 2][ar] = av0.z; As[ak + 3][ar] = av0.w;
        As[ak + 4][ar] = av1.x; As[ak + 5][ar] = av1.y;
        As[ak + 6][ar] = av1.z; As[ak + 7][ar] = av1.w;
        Bs[ak + 0][ar] = bv0.x; Bs[ak + 1][ar] = bv0.y;
        Bs[ak + 2][ar] = bv0.z; Bs[ak + 3][ar] = bv0.w;
        Bs[ak + 4][ar] = bv1.x; Bs[ak + 5][ar] = bv1.y;
        Bs[ak + 6][ar] = bv1.z; Bs[ak + 7][ar] = bv1.w;
        __syncthreads();
#pragma unroll
        for (int k = 0; k < GBK; k++) {
            // packed row pairs (contiguous floats in As row k)
            ulonglong2 a01 = *reinterpret_cast<const ulonglong2*>(&As[k][tr]);
            ulonglong2 a23 = *reinterpret_cast<const ulonglong2*>(&As[k][tr + 4]);
            u64 ap[4] = {a01.x, a01.y, a23.x, a23.y};
            float4 b0 = *reinterpret_cast<const float4*>(&Bs[k][tc]);
            float4 b1 = *reinterpret_cast<const float4*>(&Bs[k][tc + 4]);
            u64 bs[8];
            bs[0] = f2u2(b0.x, b0.x); bs[1] = f2u2(b0.y, b0.y);
            bs[2] = f2u2(b0.z, b0.z); bs[3] = f2u2(b0.w, b0.w);
            bs[4] = f2u2(b1.x, b1.x); bs[5] = f2u2(b1.y, b1.y);
            bs[6] = f2u2(b1.z, b1.z); bs[7] = f2u2(b1.w, b1.w);
#pragma unroll
            for (int u = 0; u < 4; u++)
#pragma unroll
                for (int v = 0; v < 8; v++)
                    ffma2(acc2[u][v], ap[u], bs[v]);
        }
        __syncthreads();
    }

#pragma unroll
    for (int u = 0; u < 4; u++) {
        const int r0 = row0 + tr + 2 * u;
        float lo[8], hi[8];
#pragma unroll
        for (int v = 0; v < 8; v++) {
            float2 t = u2f2(acc2[u][v]);
            lo[v] = t.x; hi[v] = t.y;
        }
#pragma unroll
        for (int half = 0; half < 2; half++) {
            const int c = col0 + tc + half * 4;
            float4 h0 = *reinterpret_cast<const float4*>(&Hin[r0 * IN_SZ + c]);
            float4 h1 = *reinterpret_cast<const float4*>(&Hin[(r0 + 1) * IN_SZ + c]);
            float4 o0, o1;
            o0.x = h0.x + lo[half*4+0]; o0.y = h0.y + lo[half*4+1];
            o0.z = h0.z + lo[half*4+2]; o0.w = h0.w + lo[half*4+3];
            o1.x = h1.x + hi[half*4+0]; o1.y = h1.y + hi[half*4+1];
            o1.z = h1.z + hi[half*4+2]; o1.w = h1.w + hi[half*4+3];
            *reinterpret_cast<float4*>(&out[r0 * IN_SZ + c]) = o0;
            *reinterpret_cast<float4*>(&out[(r0 + 1) * IN_SZ + c]) = o1;
        }
    }
}

extern "C" void kernel_launch(void* const* d_in, const int* in_sizes, int n_in,
                              void* d_out, int out_size) {
    const float* h_in  = (const float*)d_in[0];
    const float* W_y   = (const float*)d_in[1];
    const float* W_q   = (const float*)d_in[2];
    const float* W_k   = (const float*)d_in[3];
    const float* w_b   = (const float*)d_in[4];
    const float* W_out = (const float*)d_in[5];
    const float* sWy   = (const float*)d_in[6];
    const float* sWq   = (const float*)d_in[7];
    const float* sWk   = (const float*)d_in[8];
    const float* swb   = (const float*)d_in[9];
    const float* Fw    = (const float*)d_in[10];

    srwm_scan_kernel<<<B_SZ * H_SZ, NTHREADS>>>(
        h_in, W_y, W_q, W_k, w_b, sWy, sWq, sWk, swb, Fw);

    dim3 grid((T_LEN * B_SZ) / GBM, IN_SZ / GBN);
    proj_kernel<<<grid, 256>>>(W_out, h_in, (float*)d_out);
}